// round 2
// baseline (speedup 1.0000x reference)
#include <cuda_runtime.h>
#include <math.h>

#define NN 100000
#define NE 1600000
#define HID 128
#define HEADS 4
#define NL 3

// ---------------- device scratch (static: no allocation) ----------------
__device__ float g_x[NN * HID];                 // 51.2 MB current features
__device__ float g_h[NN * HEADS * HID];         // 204.8 MB  h = x @ Wg
__device__ float g_as[NN * HEADS];
__device__ float g_ad[NN * HEADS];
__device__ float g_ew[NL * NE];                 // per-layer scalar edge weights
__device__ float g_wvec[NL * 64];
__device__ float g_bemean[NL];
__device__ float g_ewsum[NL];
__device__ int   g_deg[NN];
__device__ int   g_start[NN + 1];
__device__ int   g_cursor[NN];
__device__ int   g_csrc[NE];
__device__ int   g_ceid[NE];

// ---------------- tiny precompute: wvec = row-mean of We, be-mean ----------------
__global__ void prep_kernel(const float* __restrict__ We, const float* __restrict__ be) {
    int t = threadIdx.x;
    if (t < NL * 64) {
        const float* w = We + t * 128;     // We[l][k][:] row, t = l*64+k
        float s = 0.f;
        #pragma unroll 8
        for (int j = 0; j < 128; j++) s += w[j];
        g_wvec[t] = s * (1.f / 128.f);
    } else if (t < NL * 64 + NL) {
        int l = t - NL * 64;
        float s = 0.f;
        for (int j = 0; j < 128; j++) s += be[l * 128 + j];
        g_bemean[l] = s * (1.f / 128.f);
        g_ewsum[l] = 0.f;
    }
}

__global__ void zero_deg_kernel() {
    int i = blockIdx.x * blockDim.x + threadIdx.x;
    if (i < NN) g_deg[i] = 0;
}

// ---------------- edge weights for all 3 layers in one pass over edge_attr ----------------
__global__ void ew_kernel(const float* __restrict__ ea) {
    __shared__ float tile[64 * 68];
    __shared__ float wv[NL * 64];
    __shared__ float ssum[NL];
    int tid = threadIdx.x;
    if (tid < NL * 64) wv[tid] = g_wvec[tid];
    if (tid < NL) ssum[tid] = 0.f;
    int e0 = blockIdx.x * 64;                       // NE % 64 == 0, no guards
    #pragma unroll
    for (int i = 0; i < 4; i++) {
        int f = tid + i * 256;
        int r = f >> 4, c4 = (f & 15) * 4;
        float4 v = *(const float4*)(ea + (size_t)(e0 + r) * 64 + c4);
        *(float4*)&tile[r * 68 + c4] = v;
    }
    __syncthreads();
    int g = tid & 3, el = tid >> 2;                 // 4 threads per edge
    float p0 = 0.f, p1 = 0.f, p2 = 0.f;
    int kb = g * 16;
    #pragma unroll
    for (int j = 0; j < 16; j++) {
        float v = tile[el * 68 + kb + j];
        p0 += v * wv[kb + j];
        p1 += v * wv[64 + kb + j];
        p2 += v * wv[128 + kb + j];
    }
    #pragma unroll
    for (int o = 1; o <= 2; o <<= 1) {
        p0 += __shfl_xor_sync(0xffffffffu, p0, o);
        p1 += __shfl_xor_sync(0xffffffffu, p1, o);
        p2 += __shfl_xor_sync(0xffffffffu, p2, o);
    }
    if (g == 0) {
        int e = e0 + el;
        float w0 = p0 + g_bemean[0];
        float w1 = p1 + g_bemean[1];
        float w2 = p2 + g_bemean[2];
        g_ew[e] = w0;
        g_ew[NE + e] = w1;
        g_ew[2 * NE + e] = w2;
        atomicAdd(&ssum[0], w0);
        atomicAdd(&ssum[1], w1);
        atomicAdd(&ssum[2], w2);
    }
    __syncthreads();
    if (tid < NL) atomicAdd(&g_ewsum[tid], ssum[tid]);
}

// ---------------- CSR build: histogram, scan, fill ----------------
__global__ void hist_kernel(const int* __restrict__ dst) {
    int e = blockIdx.x * blockDim.x + threadIdx.x;
    if (e < NE) atomicAdd(&g_deg[dst[e]], 1);
}

__global__ void scan_kernel() {
    __shared__ int sh[1024];
    int t = threadIdx.x;
    const int CH = (NN + 1023) / 1024;   // 98
    int begin = t * CH;
    int end = begin + CH; if (end > NN) end = NN;
    int s = 0;
    for (int i = begin; i < end && begin < NN; i++) s += g_deg[i];
    if (begin >= NN) s = 0;
    sh[t] = s;
    __syncthreads();
    for (int off = 1; off < 1024; off <<= 1) {
        int v = 0;
        if (t >= off) v = sh[t - off];
        __syncthreads();
        sh[t] += v;
        __syncthreads();
    }
    int run = sh[t] - s;   // exclusive prefix
    for (int i = begin; i < end && begin < NN; i++) {
        g_start[i] = run;
        g_cursor[i] = run;
        run += g_deg[i];
    }
    if (t == 1023) g_start[NN] = sh[1023];
}

__global__ void fill_kernel(const int* __restrict__ src, const int* __restrict__ dst) {
    int e = blockIdx.x * blockDim.x + threadIdx.x;
    if (e < NE) {
        int d = dst[e];
        int pos = atomicAdd(&g_cursor[d], 1);
        g_csrc[pos] = src[e];
        g_ceid[pos] = e;
    }
}

// ---------------- fp32 GEMM: C[M=NN, N] = A[NN,128] @ B[128,N] (+bias, relu) ----------------
template <bool BR>
__global__ void gemm_k(const float* __restrict__ A, const float* __restrict__ B,
                       float* __restrict__ C, const float* __restrict__ bias, int N) {
    __shared__ float As[64][68];
    __shared__ float Bs[64][68];
    int tid = threadIdx.x;
    int m0 = blockIdx.y * 64, n0 = blockIdx.x * 64;
    int tx = tid & 15, ty = tid >> 4;
    float acc[4][4] = {};
    for (int kc = 0; kc < 128; kc += 64) {
        #pragma unroll
        for (int i = 0; i < 4; i++) {
            int f = tid + i * 256;
            int r = f >> 4, c4 = (f & 15) * 4;
            float4 v = make_float4(0.f, 0.f, 0.f, 0.f);
            int gr = m0 + r;
            if (gr < NN) v = *(const float4*)(A + (size_t)gr * 128 + kc + c4);
            *(float4*)&As[r][c4] = v;
        }
        #pragma unroll
        for (int i = 0; i < 4; i++) {
            int f = tid + i * 256;
            int r = f >> 4, c4 = (f & 15) * 4;
            *(float4*)&Bs[r][c4] = *(const float4*)(B + (size_t)(kc + r) * N + n0 + c4);
        }
        __syncthreads();
        #pragma unroll 16
        for (int k = 0; k < 64; k++) {
            float4 b4 = *(float4*)&Bs[k][tx * 4];
            float a0 = As[ty * 4 + 0][k];
            float a1 = As[ty * 4 + 1][k];
            float a2 = As[ty * 4 + 2][k];
            float a3 = As[ty * 4 + 3][k];
            acc[0][0] += a0 * b4.x; acc[0][1] += a0 * b4.y; acc[0][2] += a0 * b4.z; acc[0][3] += a0 * b4.w;
            acc[1][0] += a1 * b4.x; acc[1][1] += a1 * b4.y; acc[1][2] += a1 * b4.z; acc[1][3] += a1 * b4.w;
            acc[2][0] += a2 * b4.x; acc[2][1] += a2 * b4.y; acc[2][2] += a2 * b4.z; acc[2][3] += a2 * b4.w;
            acc[3][0] += a3 * b4.x; acc[3][1] += a3 * b4.y; acc[3][2] += a3 * b4.z; acc[3][3] += a3 * b4.w;
        }
        __syncthreads();
    }
    #pragma unroll
    for (int i = 0; i < 4; i++) {
        int row = m0 + ty * 4 + i;
        if (row < NN) {
            float4 o = make_float4(acc[i][0], acc[i][1], acc[i][2], acc[i][3]);
            if (BR) {
                float4 bv = *(const float4*)(bias + n0 + tx * 4);
                o.x = fmaxf(o.x + bv.x, 0.f);
                o.y = fmaxf(o.y + bv.y, 0.f);
                o.z = fmaxf(o.z + bv.z, 0.f);
                o.w = fmaxf(o.w + bv.w, 0.f);
            }
            *(float4*)(C + (size_t)row * N + n0 + tx * 4) = o;
        }
    }
}

// ---------------- per-node attention projections a_s, a_d ----------------
__global__ void att_kernel(const float* __restrict__ atts, const float* __restrict__ attd) {
    int lane = threadIdx.x & 31;
    int n = blockIdx.x * 8 + (threadIdx.x >> 5);
    if (n >= NN) return;
    const float* hrow = g_h + (size_t)n * 512 + lane * 4;
    float ps[4], pd[4];
    #pragma unroll
    for (int h = 0; h < 4; h++) {
        float4 hv = *(const float4*)(hrow + h * 128);
        float4 ws = *(const float4*)(atts + h * 128 + lane * 4);
        float4 wd = *(const float4*)(attd + h * 128 + lane * 4);
        ps[h] = hv.x * ws.x + hv.y * ws.y + hv.z * ws.z + hv.w * ws.w;
        pd[h] = hv.x * wd.x + hv.y * wd.y + hv.z * wd.z + hv.w * wd.w;
    }
    #pragma unroll
    for (int o = 16; o; o >>= 1) {
        #pragma unroll
        for (int h = 0; h < 4; h++) {
            ps[h] += __shfl_xor_sync(0xffffffffu, ps[h], o);
            pd[h] += __shfl_xor_sync(0xffffffffu, pd[h], o);
        }
    }
    if (lane == 0) {
        *(float4*)(g_as + n * 4) = make_float4(ps[0], ps[1], ps[2], ps[3]);
        *(float4*)(g_ad + n * 4) = make_float4(pd[0], pd[1], pd[2], pd[3]);
    }
}

// ---------------- fused: online-softmax aggregation + head-mean + bias + LN + residual relu ----
__global__ void agg_kernel(int l, const float* __restrict__ bg,
                           const float* __restrict__ gam, const float* __restrict__ bet,
                           const float* __restrict__ xin, float* __restrict__ xout) {
    int lane = threadIdx.x & 31;
    int n = blockIdx.x * 8 + (threadIdx.x >> 5);
    if (n >= NN) return;

    const float* ewl = g_ew + (size_t)l * NE;
    float ewmean = g_ewsum[l] * (1.f / NE);
    float4 ad4 = *(const float4*)(g_ad + n * 4);
    float ad[4] = {ad4.x, ad4.y, ad4.z, ad4.w};

    float m[4], den[4], acc[4][4];
    #pragma unroll
    for (int h = 0; h < 4; h++) {
        m[h] = -1e30f; den[h] = 0.f;
        acc[h][0] = acc[h][1] = acc[h][2] = acc[h][3] = 0.f;
    }

    int p = g_start[n];
    int pend = g_start[n + 1];
    int s = n;            // self-loop first
    float ew = ewmean;

    for (;;) {
        float4 as4 = *(const float4*)(g_as + s * 4);
        float asv[4] = {as4.x, as4.y, as4.z, as4.w};
        float ex[4], sc[4];
        #pragma unroll
        for (int h = 0; h < 4; h++) {
            float z = asv[h] + ad[h] + ew;
            z = (z > 0.f) ? z : 0.2f * z;            // leaky relu
            float nm = fmaxf(m[h], z);
            sc[h] = __expf(m[h] - nm);
            ex[h] = __expf(z - nm);
            den[h] = den[h] * sc[h] + ex[h];
            m[h] = nm;
        }
        const float* hrow = g_h + (size_t)s * 512 + lane * 4;
        #pragma unroll
        for (int h = 0; h < 4; h++) {
            float4 hv = *(const float4*)(hrow + h * 128);
            acc[h][0] = acc[h][0] * sc[h] + ex[h] * hv.x;
            acc[h][1] = acc[h][1] * sc[h] + ex[h] * hv.y;
            acc[h][2] = acc[h][2] * sc[h] + ex[h] * hv.z;
            acc[h][3] = acc[h][3] * sc[h] + ex[h] * hv.w;
        }
        if (p >= pend) break;
        s = g_csrc[p];
        ew = ewl[g_ceid[p]];
        p++;
    }

    float i0 = 1.f / den[0], i1 = 1.f / den[1], i2 = 1.f / den[2], i3 = 1.f / den[3];
    float4 bgv = *(const float4*)(bg + lane * 4);
    float bga[4] = {bgv.x, bgv.y, bgv.z, bgv.w};
    float v[4];
    #pragma unroll
    for (int j = 0; j < 4; j++) {
        v[j] = 0.25f * (acc[0][j] * i0 + acc[1][j] * i1 + acc[2][j] * i2 + acc[3][j] * i3) + bga[j];
    }
    // layer norm over 128 channels (4 per lane)
    float s1 = v[0] + v[1] + v[2] + v[3];
    #pragma unroll
    for (int o = 16; o; o >>= 1) s1 += __shfl_xor_sync(0xffffffffu, s1, o);
    float mu = s1 * (1.f / 128.f);
    float q = 0.f;
    #pragma unroll
    for (int j = 0; j < 4; j++) { float d = v[j] - mu; q += d * d; }
    #pragma unroll
    for (int o = 16; o; o >>= 1) q += __shfl_xor_sync(0xffffffffu, q, o);
    float rstd = rsqrtf(q * (1.f / 128.f) + 1e-5f);

    float4 gv = *(const float4*)(gam + lane * 4);
    float4 bv = *(const float4*)(bet + lane * 4);
    float4 xo = *(const float4*)(xin + (size_t)n * 128 + lane * 4);
    float4 r;
    r.x = fmaxf(xo.x + (v[0] - mu) * rstd * gv.x + bv.x, 0.f);
    r.y = fmaxf(xo.y + (v[1] - mu) * rstd * gv.y + bv.y, 0.f);
    r.z = fmaxf(xo.z + (v[2] - mu) * rstd * gv.z + bv.z, 0.f);
    r.w = fmaxf(xo.w + (v[3] - mu) * rstd * gv.w + bv.w, 0.f);
    *(float4*)(xout + (size_t)n * 128 + lane * 4) = r;
}

// ---------------- host ----------------
extern "C" void kernel_launch(void* const* d_in, const int* in_sizes, int n_in,
                              void* d_out, int out_size) {
    const float* nf   = (const float*)d_in[0];
    const int*   ei   = (const int*)d_in[1];
    const float* ea   = (const float*)d_in[2];
    const float* W0   = (const float*)d_in[3];
    const float* b0   = (const float*)d_in[4];
    const float* We   = (const float*)d_in[5];
    const float* be   = (const float*)d_in[6];
    const float* Wg   = (const float*)d_in[7];
    const float* atts = (const float*)d_in[8];
    const float* attd = (const float*)d_in[9];
    const float* bg   = (const float*)d_in[10];
    const float* gam  = (const float*)d_in[11];
    const float* bet  = (const float*)d_in[12];
    float* out = (float*)d_out;
    const int* src = ei;
    const int* dst = ei + NE;

    void *px, *ph;
    cudaGetSymbolAddress(&px, g_x);
    cudaGetSymbolAddress(&ph, g_h);
    float* gx = (float*)px;
    float* gh = (float*)ph;

    prep_kernel<<<1, 256>>>(We, be);
    zero_deg_kernel<<<(NN + 255) / 256, 256>>>();
    ew_kernel<<<NE / 64, 256>>>(ea);
    hist_kernel<<<(NE + 255) / 256, 256>>>(dst);
    scan_kernel<<<1, 1024>>>();
    fill_kernel<<<(NE + 255) / 256, 256>>>(src, dst);

    // encoder: x = relu(nf @ W0 + b0)
    gemm_k<true><<<dim3(128 / 64, (NN + 63) / 64), 256>>>(nf, W0, gx, b0, 128);

    int nblk = (NN + 7) / 8;
    for (int l = 0; l < NL; l++) {
        gemm_k<false><<<dim3(512 / 64, (NN + 63) / 64), 256>>>(
            gx, Wg + (size_t)l * 128 * 512, gh, nullptr, 512);
        att_kernel<<<nblk, 256>>>(atts + (size_t)l * HEADS * HID, attd + (size_t)l * HEADS * HID);
        float* dstx = (l == NL - 1) ? out : gx;
        agg_kernel<<<nblk, 256>>>(l, bg + (size_t)l * HID, gam + (size_t)l * HID,
                                  bet + (size_t)l * HID, gx, dstx);
    }
    (void)in_sizes; (void)n_in; (void)out_size;
}

// round 5
// speedup vs baseline: 1.0802x; 1.0802x over previous
#include <cuda_runtime.h>
#include <cuda_fp16.h>
#include <math.h>

#define NN 100000
#define NE 1600000
#define HID 128
#define HEADS 4
#define NL 3

// ---------------- device scratch (static: no allocation) ----------------
__device__ float  g_x[NN * HID];                 // 51.2 MB current features
__device__ __half g_h[NN * HEADS * HID];         // 102.4 MB  h = x @ Wg (fp16)
__device__ float  g_as[NN * HEADS];
__device__ float  g_ad[NN * HEADS];
__device__ float  g_ew[NL * NE];                 // per-layer scalar edge weights
__device__ float  g_wvec[NL * 64];
__device__ float  g_bemean[NL];
__device__ float  g_ewsum[NL];
__device__ int    g_deg[NN];
__device__ int    g_start[NN + 1];
__device__ int    g_cursor[NN];
__device__ int    g_csrc[NE];
__device__ int    g_ceid[NE];

// ---------------- tiny precompute: wvec = row-mean of We, be-mean ----------------
__global__ void prep_kernel(const float* __restrict__ We, const float* __restrict__ be) {
    int t = threadIdx.x;
    if (t < NL * 64) {
        const float* w = We + t * 128;     // We[l][k][:] row, t = l*64+k
        float s = 0.f;
        #pragma unroll 8
        for (int j = 0; j < 128; j++) s += w[j];
        g_wvec[t] = s * (1.f / 128.f);
    } else if (t < NL * 64 + NL) {
        int l = t - NL * 64;
        float s = 0.f;
        for (int j = 0; j < 128; j++) s += be[l * 128 + j];
        g_bemean[l] = s * (1.f / 128.f);
        g_ewsum[l] = 0.f;
    }
}

__global__ void zero_deg_kernel() {
    int i = blockIdx.x * blockDim.x + threadIdx.x;
    if (i < NN) g_deg[i] = 0;
}

// ---------------- edge weights for all 3 layers in one pass over edge_attr ----------------
__global__ void ew_kernel(const float* __restrict__ ea) {
    __shared__ float tile[64 * 68];
    __shared__ float wv[NL * 64];
    __shared__ float ssum[NL];
    int tid = threadIdx.x;
    if (tid < NL * 64) wv[tid] = g_wvec[tid];
    if (tid < NL) ssum[tid] = 0.f;
    int e0 = blockIdx.x * 64;                       // NE % 64 == 0, no guards
    #pragma unroll
    for (int i = 0; i < 4; i++) {
        int f = tid + i * 256;
        int r = f >> 4, c4 = (f & 15) * 4;
        float4 v = *(const float4*)(ea + (size_t)(e0 + r) * 64 + c4);
        *(float4*)&tile[r * 68 + c4] = v;
    }
    __syncthreads();
    int g = tid & 3, el = tid >> 2;                 // 4 threads per edge
    float p0 = 0.f, p1 = 0.f, p2 = 0.f;
    int kb = g * 16;
    #pragma unroll
    for (int j = 0; j < 16; j++) {
        float v = tile[el * 68 + kb + j];
        p0 += v * wv[kb + j];
        p1 += v * wv[64 + kb + j];
        p2 += v * wv[128 + kb + j];
    }
    #pragma unroll
    for (int o = 1; o <= 2; o <<= 1) {
        p0 += __shfl_xor_sync(0xffffffffu, p0, o);
        p1 += __shfl_xor_sync(0xffffffffu, p1, o);
        p2 += __shfl_xor_sync(0xffffffffu, p2, o);
    }
    if (g == 0) {
        int e = e0 + el;
        float w0 = p0 + g_bemean[0];
        float w1 = p1 + g_bemean[1];
        float w2 = p2 + g_bemean[2];
        g_ew[e] = w0;
        g_ew[NE + e] = w1;
        g_ew[2 * NE + e] = w2;
        atomicAdd(&ssum[0], w0);
        atomicAdd(&ssum[1], w1);
        atomicAdd(&ssum[2], w2);
    }
    __syncthreads();
    if (tid < NL) atomicAdd(&g_ewsum[tid], ssum[tid]);
}

// ---------------- CSR build: histogram, scan, fill ----------------
__global__ void hist_kernel(const int* __restrict__ dst) {
    int e = blockIdx.x * blockDim.x + threadIdx.x;
    if (e < NE) atomicAdd(&g_deg[dst[e]], 1);
}

__global__ void scan_kernel() {
    __shared__ int sh[1024];
    int t = threadIdx.x;
    const int CH = (NN + 1023) / 1024;   // 98
    int begin = t * CH;
    int end = begin + CH; if (end > NN) end = NN;
    int s = 0;
    for (int i = begin; i < end && begin < NN; i++) s += g_deg[i];
    if (begin >= NN) s = 0;
    sh[t] = s;
    __syncthreads();
    for (int off = 1; off < 1024; off <<= 1) {
        int v = 0;
        if (t >= off) v = sh[t - off];
        __syncthreads();
        sh[t] += v;
        __syncthreads();
    }
    int run = sh[t] - s;   // exclusive prefix
    for (int i = begin; i < end && begin < NN; i++) {
        g_start[i] = run;
        g_cursor[i] = run;
        run += g_deg[i];
    }
    if (t == 1023) g_start[NN] = sh[1023];
}

__global__ void fill_kernel(const int* __restrict__ src, const int* __restrict__ dst) {
    int e = blockIdx.x * blockDim.x + threadIdx.x;
    if (e < NE) {
        int d = dst[e];
        int pos = atomicAdd(&g_cursor[d], 1);
        g_csrc[pos] = src[e];
        g_ceid[pos] = e;
    }
}

// ---------------- fp32 GEMM: C[M=NN, N] = A[NN,128] @ B[128,N] (+bias, relu) ----------------
// OT = float (encoder, bias+relu) or __half (h projection).
template <typename OT, bool BR>
__global__ void gemm_k(const float* __restrict__ A, const float* __restrict__ B,
                       OT* __restrict__ C, const float* __restrict__ bias, int N) {
    __shared__ float As[64][68];
    __shared__ float Bs[64][68];
    int tid = threadIdx.x;
    int m0 = blockIdx.y * 64, n0 = blockIdx.x * 64;
    int tx = tid & 15, ty = tid >> 4;
    float acc[4][4] = {};
    #pragma unroll 1
    for (int kc = 0; kc < 128; kc += 64) {
        #pragma unroll
        for (int i = 0; i < 4; i++) {
            int f = tid + i * 256;
            int r = f >> 4, c4 = (f & 15) * 4;
            float4 v = make_float4(0.f, 0.f, 0.f, 0.f);
            int gr = m0 + r;
            if (gr < NN) v = *(const float4*)(A + (size_t)gr * 128 + kc + c4);
            *(float4*)&As[r][c4] = v;
        }
        #pragma unroll
        for (int i = 0; i < 4; i++) {
            int f = tid + i * 256;
            int r = f >> 4, c4 = (f & 15) * 4;
            *(float4*)&Bs[r][c4] = *(const float4*)(B + (size_t)(kc + r) * N + n0 + c4);
        }
        __syncthreads();
        #pragma unroll
        for (int k = 0; k < 64; k += 4) {
            float av[4][4];
            *(float4*)av[0] = *(const float4*)&As[ty * 4 + 0][k];
            *(float4*)av[1] = *(const float4*)&As[ty * 4 + 1][k];
            *(float4*)av[2] = *(const float4*)&As[ty * 4 + 2][k];
            *(float4*)av[3] = *(const float4*)&As[ty * 4 + 3][k];
            #pragma unroll
            for (int j = 0; j < 4; j++) {
                float4 b4 = *(const float4*)&Bs[k + j][tx * 4];
                #pragma unroll
                for (int i = 0; i < 4; i++) {
                    acc[i][0] += av[i][j] * b4.x;
                    acc[i][1] += av[i][j] * b4.y;
                    acc[i][2] += av[i][j] * b4.z;
                    acc[i][3] += av[i][j] * b4.w;
                }
            }
        }
        __syncthreads();
    }
    #pragma unroll
    for (int i = 0; i < 4; i++) {
        int row = m0 + ty * 4 + i;
        if (row < NN) {
            float4 o = make_float4(acc[i][0], acc[i][1], acc[i][2], acc[i][3]);
            if (BR) {
                float4 bv = *(const float4*)(bias + n0 + tx * 4);
                o.x = fmaxf(o.x + bv.x, 0.f);
                o.y = fmaxf(o.y + bv.y, 0.f);
                o.z = fmaxf(o.z + bv.z, 0.f);
                o.w = fmaxf(o.w + bv.w, 0.f);
            }
            if constexpr (sizeof(OT) == 2) {
                __half2 lo = __floats2half2_rn(o.x, o.y);
                __half2 hi = __floats2half2_rn(o.z, o.w);
                uint2 pk;
                pk.x = *(unsigned int*)&lo;
                pk.y = *(unsigned int*)&hi;
                *(uint2*)((__half*)C + (size_t)row * N + n0 + tx * 4) = pk;
            } else {
                *(float4*)((float*)C + (size_t)row * N + n0 + tx * 4) = o;
            }
        }
    }
}

// ---------------- per-node attention projections a_s, a_d (reads fp16 h) ----------------
__global__ void att_kernel(const float* __restrict__ atts, const float* __restrict__ attd) {
    int lane = threadIdx.x & 31;
    int n = blockIdx.x * 8 + (threadIdx.x >> 5);
    if (n >= NN) return;
    const __half* hrow = g_h + (size_t)n * 512 + lane * 4;
    float ps[4], pd[4];
    #pragma unroll
    for (int h = 0; h < 4; h++) {
        uint2 raw = *(const uint2*)(hrow + h * 128);
        float2 f0 = __half22float2(*(__half2*)&raw.x);
        float2 f1 = __half22float2(*(__half2*)&raw.y);
        float4 ws = *(const float4*)(atts + h * 128 + lane * 4);
        float4 wd = *(const float4*)(attd + h * 128 + lane * 4);
        ps[h] = f0.x * ws.x + f0.y * ws.y + f1.x * ws.z + f1.y * ws.w;
        pd[h] = f0.x * wd.x + f0.y * wd.y + f1.x * wd.z + f1.y * wd.w;
    }
    #pragma unroll
    for (int o = 16; o; o >>= 1) {
        #pragma unroll
        for (int h = 0; h < 4; h++) {
            ps[h] += __shfl_xor_sync(0xffffffffu, ps[h], o);
            pd[h] += __shfl_xor_sync(0xffffffffu, pd[h], o);
        }
    }
    if (lane == 0) {
        *(float4*)(g_as + n * 4) = make_float4(ps[0], ps[1], ps[2], ps[3]);
        *(float4*)(g_ad + n * 4) = make_float4(pd[0], pd[1], pd[2], pd[3]);
    }
}

// ---------------- fused: online-softmax aggregation + head-mean + bias + LN + residual relu ----
__global__ void agg_kernel(int l, const float* __restrict__ bg,
                           const float* __restrict__ gam, const float* __restrict__ bet,
                           const float* __restrict__ xin, float* __restrict__ xout) {
    int lane = threadIdx.x & 31;
    int n = blockIdx.x * 8 + (threadIdx.x >> 5);
    if (n >= NN) return;

    const float* ewl = g_ew + (size_t)l * NE;
    float ewmean = g_ewsum[l] * (1.f / NE);
    float4 ad4 = *(const float4*)(g_ad + n * 4);
    float ad[4] = {ad4.x, ad4.y, ad4.z, ad4.w};

    float m[4], den[4], acc[4][4];
    #pragma unroll
    for (int h = 0; h < 4; h++) {
        m[h] = -1e30f; den[h] = 0.f;
        acc[h][0] = acc[h][1] = acc[h][2] = acc[h][3] = 0.f;
    }

    int p = g_start[n];
    int pend = g_start[n + 1];
    int s = n;            // self-loop first
    float ew = ewmean;

    for (;;) {
        float4 as4 = *(const float4*)(g_as + s * 4);
        float asv[4] = {as4.x, as4.y, as4.z, as4.w};
        float ex[4], sc[4];
        #pragma unroll
        for (int h = 0; h < 4; h++) {
            float z = asv[h] + ad[h] + ew;
            z = (z > 0.f) ? z : 0.2f * z;            // leaky relu
            float nm = fmaxf(m[h], z);
            sc[h] = __expf(m[h] - nm);
            ex[h] = __expf(z - nm);
            den[h] = den[h] * sc[h] + ex[h];
            m[h] = nm;
        }
        const __half* hrow = g_h + (size_t)s * 512 + lane * 4;
        #pragma unroll
        for (int h = 0; h < 4; h++) {
            uint2 raw = *(const uint2*)(hrow + h * 128);
            float2 f0 = __half22float2(*(__half2*)&raw.x);
            float2 f1 = __half22float2(*(__half2*)&raw.y);
            acc[h][0] = acc[h][0] * sc[h] + ex[h] * f0.x;
            acc[h][1] = acc[h][1] * sc[h] + ex[h] * f0.y;
            acc[h][2] = acc[h][2] * sc[h] + ex[h] * f1.x;
            acc[h][3] = acc[h][3] * sc[h] + ex[h] * f1.y;
        }
        if (p >= pend) break;
        s = g_csrc[p];
        ew = ewl[g_ceid[p]];
        p++;
    }

    float i0 = 1.f / den[0], i1 = 1.f / den[1], i2 = 1.f / den[2], i3 = 1.f / den[3];
    float4 bgv = *(const float4*)(bg + lane * 4);
    float v[4];
    float bga[4] = {bgv.x, bgv.y, bgv.z, bgv.w};
    #pragma unroll
    for (int j = 0; j < 4; j++) {
        v[j] = 0.25f * (acc[0][j] * i0 + acc[1][j] * i1 + acc[2][j] * i2 + acc[3][j] * i3) + bga[j];
    }
    // layer norm over 128 channels (4 per lane)
    float s1 = v[0] + v[1] + v[2] + v[3];
    #pragma unroll
    for (int o = 16; o; o >>= 1) s1 += __shfl_xor_sync(0xffffffffu, s1, o);
    float mu = s1 * (1.f / 128.f);
    float q = 0.f;
    #pragma unroll
    for (int j = 0; j < 4; j++) { float d = v[j] - mu; q += d * d; }
    #pragma unroll
    for (int o = 16; o; o >>= 1) q += __shfl_xor_sync(0xffffffffu, q, o);
    float rstd = rsqrtf(q * (1.f / 128.f) + 1e-5f);

    float4 gv = *(const float4*)(gam + lane * 4);
    float4 bv = *(const float4*)(bet + lane * 4);
    float4 xo = *(const float4*)(xin + (size_t)n * 128 + lane * 4);
    float4 r;
    r.x = fmaxf(xo.x + (v[0] - mu) * rstd * gv.x + bv.x, 0.f);
    r.y = fmaxf(xo.y + (v[1] - mu) * rstd * gv.y + bv.y, 0.f);
    r.z = fmaxf(xo.z + (v[2] - mu) * rstd * gv.z + bv.z, 0.f);
    r.w = fmaxf(xo.w + (v[3] - mu) * rstd * gv.w + bv.w, 0.f);
    *(float4*)(xout + (size_t)n * 128 + lane * 4) = r;
}

// ---------------- host ----------------
extern "C" void kernel_launch(void* const* d_in, const int* in_sizes, int n_in,
                              void* d_out, int out_size) {
    const float* nf   = (const float*)d_in[0];
    const int*   ei   = (const int*)d_in[1];
    const float* ea   = (const float*)d_in[2];
    const float* W0   = (const float*)d_in[3];
    const float* b0   = (const float*)d_in[4];
    const float* We   = (const float*)d_in[5];
    const float* be   = (const float*)d_in[6];
    const float* Wg   = (const float*)d_in[7];
    const float* atts = (const float*)d_in[8];
    const float* attd = (const float*)d_in[9];
    const float* bg   = (const float*)d_in[10];
    const float* gam  = (const float*)d_in[11];
    const float* bet  = (const float*)d_in[12];
    float* out = (float*)d_out;
    const int* src = ei;
    const int* dst = ei + NE;

    void *px, *ph;
    cudaGetSymbolAddress(&px, g_x);
    cudaGetSymbolAddress(&ph, g_h);
    float*  gx = (float*)px;
    __half* gh = (__half*)ph;

    const int MB = (NN + 63) / 64;      // 1563
    const int nblk = (NN + 7) / 8;

    // Order chosen so ncu's capture slot (-s 5 -c 1) lands on the layer-0 Wg GEMM.
    prep_kernel<<<1, 256>>>(We, be);                                         // 1
    gemm_k<float, true><<<dim3(2, MB), 256>>>(nf, W0, gx, b0, 128);          // 2: encoder
    zero_deg_kernel<<<(NN + 255) / 256, 256>>>();                            // 3
    ew_kernel<<<NE / 64, 256>>>(ea);                                         // 4
    hist_kernel<<<(NE + 255) / 256, 256>>>(dst);                             // 5
    gemm_k<__half, false><<<dim3(8, MB), 256>>>(gx, Wg, gh, nullptr, 512);   // 6: BIG GEMM (profiled)
    scan_kernel<<<1, 1024>>>();                                              // 7
    fill_kernel<<<(NE + 255) / 256, 256>>>(src, dst);                        // 8
    att_kernel<<<nblk, 256>>>(atts, attd);                                   // 9
    agg_kernel<<<nblk, 256>>>(0, bg, gam, bet, gx, gx);                      // 10

    for (int l = 1; l < NL; l++) {
        gemm_k<__half, false><<<dim3(8, MB), 256>>>(
            gx, Wg + (size_t)l * 128 * 512, gh, nullptr, 512);
        att_kernel<<<nblk, 256>>>(atts + (size_t)l * HEADS * HID, attd + (size_t)l * HEADS * HID);
        float* dstx = (l == NL - 1) ? out : gx;
        agg_kernel<<<nblk, 256>>>(l, bg + (size_t)l * HID, gam + (size_t)l * HID,
                                  bet + (size_t)l * HID, gx, dstx);
    }
    (void)in_sizes; (void)n_in; (void)out_size;
}